// round 1
// baseline (speedup 1.0000x reference)
#include <cuda_runtime.h>
#include <cuda_fp16.h>
#include <cstdint>
#include <cstddef>

#define B_DIM   4096
#define I_DIM   256
#define O_DIM   256
#define G_DIM   8
#define K_BASIS (I_DIM * G_DIM * G_DIM)     /* 16384 */
#define K_TOT   (K_BASIS + 2 * I_DIM)       /* 16896 */
#define N_TOT   (2 * O_DIM)                 /* 512   */

#define BM 128
#define BN 128
#define BK 32
#define STAGES 3
#define NITER (K_TOT / BK)                  /* 528 */

// ---------------- device scratch (no allocations allowed) ----------------
__device__ __align__(128) __half g_A[(size_t)B_DIM * K_TOT];   // 138 MB fp16 A matrix
__device__ __align__(128) __half g_Wt[(size_t)N_TOT * K_TOT];  // 17 MB packed W^T [n][k]
__device__ float g_bias[N_TOT];

// ---------------- helpers ----------------
__device__ __forceinline__ void cp_async16(void* smem, const void* gmem) {
    uint32_t s = (uint32_t)__cvta_generic_to_shared(smem);
    asm volatile("cp.async.cg.shared.global [%0], [%1], 16;\n" :: "r"(s), "l"(gmem));
}
#define CP_COMMIT() asm volatile("cp.async.commit_group;\n" ::: "memory")
#define CP_WAIT(N)  asm volatile("cp.async.wait_group %0;\n" :: "n"(N) : "memory")

__device__ __forceinline__ void mma16816(float* d, const uint32_t* a, const uint32_t* b) {
    asm volatile(
        "mma.sync.aligned.m16n8k16.row.col.f32.f16.f16.f32 "
        "{%0,%1,%2,%3}, {%4,%5,%6,%7}, {%8,%9}, {%0,%1,%2,%3};\n"
        : "+f"(d[0]), "+f"(d[1]), "+f"(d[2]), "+f"(d[3])
        : "r"(a[0]), "r"(a[1]), "r"(a[2]), "r"(a[3]), "r"(b[0]), "r"(b[1]));
}

// ---------------- kernel 1: bias vector (sum over i of silu biases) ----------------
__global__ void bias_kernel(const float* __restrict__ br, const float* __restrict__ bi) {
    int n = blockIdx.x * blockDim.x + threadIdx.x;
    if (n >= N_TOT) return;
    const float* src = (n < O_DIM) ? br : bi;
    int o = n & (O_DIM - 1);
    float s = 0.f;
    for (int i = 0; i < I_DIM; ++i) s += src[i * O_DIM + o];
    g_bias[n] = s;
}

// ---------------- kernel 2: pack W^T [n][k] in fp16 ----------------
// k < 16384      : rbf weights, k = i*64 + u*8 + v
// 16384..16639   : s_re rows  -> [Wr | Wi]
// 16640..16895   : s_im rows  -> [-Wi | Wr]
__global__ void pack_kernel(const float* __restrict__ rw, const float* __restrict__ cw,
                            const float* __restrict__ swr, const float* __restrict__ swi) {
    int gid = blockIdx.x * blockDim.x + threadIdx.x;  // K_TOT multiple of 256 -> no straddle
    int n = gid / K_TOT;
    int k = gid - n * K_TOT;
    int o = n & (O_DIM - 1);
    bool re = (n < O_DIM);
    float val;
    if (k < K_BASIS) {
        int i = k >> 6, uv = k & 63;
        const float* w = re ? rw : cw;
        val = w[((size_t)(i * O_DIM + o)) * 64 + uv];
    } else if (k < K_BASIS + I_DIM) {
        int i = k - K_BASIS;
        val = re ? swr[i * O_DIM + o] : swi[i * O_DIM + o];
    } else {
        int i = k - K_BASIS - I_DIM;
        val = re ? -swi[i * O_DIM + o] : swr[i * O_DIM + o];
    }
    g_Wt[(size_t)n * K_TOT + k] = __float2half(val);
}

// ---------------- kernel 3: materialize A (rank-1 basis expansion + silu) ----------------
__global__ void basis_kernel(const float* __restrict__ x_re, const float* __restrict__ x_im) {
    int b = blockIdx.x;
    int i = threadIdx.x;  // 256 threads
    float xr = x_re[b * I_DIM + i];
    float xi = x_im[b * I_DIM + i];
    float eu[8], ev[8];
#pragma unroll
    for (int u = 0; u < 8; ++u) {
        float lu = -2.0f + (float)u * (4.0f / 7.0f);
        float dr = xr - lu;  eu[u] = __expf(-dr * dr);
        float di = xi - lu;  ev[u] = __expf(-di * di);
    }
    __half2* dst = (__half2*)(g_A + (size_t)b * K_TOT + (size_t)i * 64);
#pragma unroll
    for (int u = 0; u < 8; ++u) {
#pragma unroll
        for (int v = 0; v < 8; v += 2) {
            dst[(u * 8 + v) >> 1] = __floats2half2_rn(eu[u] * ev[v], eu[u] * ev[v + 1]);
        }
    }
    float sr = xr / (1.f + __expf(-xr));
    float si = xi / (1.f + __expf(-xi));
    g_A[(size_t)b * K_TOT + K_BASIS + i]          = __float2half(sr);
    g_A[(size_t)b * K_TOT + K_BASIS + I_DIM + i]  = __float2half(si);
}

// ---------------- kernel 4: GEMM C = A * W^T + bias, epilogue writes (B,O,2) ----------------
__device__ __forceinline__ void copy_tile(__half* sA_s, __half* sB_s,
                                          const __half* gA, const __half* gB,
                                          int k0, int tid) {
#pragma unroll
    for (int r = 0; r < 2; ++r) {
        int cc = tid + r * 256;            // 512 16B-chunk slots per operand tile
        int row = cc >> 2, ch = cc & 3;
        int pch = ch ^ ((row >> 1) & 3);   // 16B-granularity XOR swizzle
        cp_async16(sA_s + row * BK + pch * 8, gA + (size_t)row * K_TOT + k0 + ch * 8);
        cp_async16(sB_s + row * BK + pch * 8, gB + (size_t)row * K_TOT + k0 + ch * 8);
    }
}

__global__ __launch_bounds__(256, 1)
void gemm_kernel(float* __restrict__ out) {
    __shared__ alignas(128) __half sA[STAGES][BM * BK];
    __shared__ alignas(128) __half sB[STAGES][BN * BK];

    int tid  = threadIdx.x;
    int bm   = blockIdx.x * BM;
    int bn   = blockIdx.y * BN;
    int warp = tid >> 5, lane = tid & 31;
    int wm = (warp >> 2) * 64;   // warp M offset (0,64)
    int wn = (warp & 3) * 32;    // warp N offset (0..96)
    int g  = lane >> 2, t = lane & 3;

    const __half* gA = g_A  + (size_t)bm * K_TOT;
    const __half* gB = g_Wt + (size_t)bn * K_TOT;

    float acc[4][4][4];
#pragma unroll
    for (int mi = 0; mi < 4; ++mi)
#pragma unroll
        for (int ni = 0; ni < 4; ++ni)
#pragma unroll
            for (int c = 0; c < 4; ++c) acc[mi][ni][c] = 0.f;

    // prologue: fill STAGES-1 stages
    copy_tile(sA[0], sB[0], gA, gB, 0, tid);      CP_COMMIT();
    copy_tile(sA[1], sB[1], gA, gB, BK, tid);     CP_COMMIT();

    for (int kt = 0; kt < NITER; ++kt) {
        CP_WAIT(STAGES - 2);
        __syncthreads();
        {
            int knext = kt + STAGES - 1;
            if (knext < NITER)
                copy_tile(sA[knext % STAGES], sB[knext % STAGES], gA, gB, knext * BK, tid);
            CP_COMMIT();
        }
        int s = kt % STAGES;
        const __half* As = sA[s];
        const __half* Bs = sB[s];

#pragma unroll
        for (int ks = 0; ks < 2; ++ks) {           // two k16 steps per BK=32
            uint32_t af[4][4];
            uint32_t bf[4][2];
#pragma unroll
            for (int mi = 0; mi < 4; ++mi) {
                int r0 = wm + mi * 16 + g;         // row & row+8 share swizzle bits
                int sw = (r0 >> 1) & 3;
                int c0 = (ks * 2)     ^ sw;
                int c1 = (ks * 2 + 1) ^ sw;
                af[mi][0] = *(const uint32_t*)(As + r0 * BK       + c0 * 8 + 2 * t);
                af[mi][1] = *(const uint32_t*)(As + (r0 + 8) * BK + c0 * 8 + 2 * t);
                af[mi][2] = *(const uint32_t*)(As + r0 * BK       + c1 * 8 + 2 * t);
                af[mi][3] = *(const uint32_t*)(As + (r0 + 8) * BK + c1 * 8 + 2 * t);
            }
#pragma unroll
            for (int ni = 0; ni < 4; ++ni) {
                int col = wn + ni * 8 + g;
                int sw = (col >> 1) & 3;
                int c0 = (ks * 2)     ^ sw;
                int c1 = (ks * 2 + 1) ^ sw;
                bf[ni][0] = *(const uint32_t*)(Bs + col * BK + c0 * 8 + 2 * t);
                bf[ni][1] = *(const uint32_t*)(Bs + col * BK + c1 * 8 + 2 * t);
            }
#pragma unroll
            for (int mi = 0; mi < 4; ++mi)
#pragma unroll
                for (int ni = 0; ni < 4; ++ni)
                    mma16816(acc[mi][ni], af[mi], bf[ni]);
        }
    }

    // epilogue: out[(b*O + o)*2 + part] = acc + bias[n]
#pragma unroll
    for (int mi = 0; mi < 4; ++mi) {
#pragma unroll
        for (int ni = 0; ni < 4; ++ni) {
            int row0 = bm + wm + mi * 16 + g;
            int col0 = bn + wn + ni * 8 + 2 * t;
            float b0 = g_bias[col0];
            float b1 = g_bias[col0 + 1];
            int o0 = col0 & (O_DIM - 1);
            int part = col0 >> 8;          // whole 128-wide tile is same part
            size_t base0 = ((size_t)row0 * O_DIM + o0) * 2 + part;
            size_t base8 = ((size_t)(row0 + 8) * O_DIM + o0) * 2 + part;
            out[base0]     = acc[mi][ni][0] + b0;
            out[base0 + 2] = acc[mi][ni][1] + b1;
            out[base8]     = acc[mi][ni][2] + b0;
            out[base8 + 2] = acc[mi][ni][3] + b1;
        }
    }
}

// ---------------- launch ----------------
extern "C" void kernel_launch(void* const* d_in, const int* in_sizes, int n_in,
                              void* d_out, int out_size) {
    const float* x_re = (const float*)d_in[0];
    const float* x_im = (const float*)d_in[1];
    const float* rw   = (const float*)d_in[2];
    const float* cw   = (const float*)d_in[3];
    const float* swr  = (const float*)d_in[4];
    const float* swi  = (const float*)d_in[5];
    const float* sbr  = (const float*)d_in[6];
    const float* sbi  = (const float*)d_in[7];
    float* out = (float*)d_out;

    bias_kernel<<<2, 256>>>(sbr, sbi);
    pack_kernel<<<(N_TOT * K_TOT) / 256, 256>>>(rw, cw, swr, swi);
    basis_kernel<<<B_DIM, I_DIM>>>(x_re, x_im);

    dim3 grid(B_DIM / BM, N_TOT / BN);   // 32 x 4 = 128 CTAs
    gemm_kernel<<<grid, 256>>>(out);
}

// round 6
// speedup vs baseline: 1.2724x; 1.2724x over previous
#include <cuda_runtime.h>
#include <cuda_fp16.h>
#include <cstdint>
#include <cstddef>

#define B_DIM   4096
#define I_DIM   256
#define O_DIM   256
#define K_BASIS (I_DIM * 64)                /* 16384 */
#define K_TOT   (K_BASIS + 2 * I_DIM)       /* 16896 */
#define N_TOT   (2 * O_DIM)                 /* 512   */

#define BM 128
#define BN 128
#define BK 64                                /* halves; 128 bytes per row */
#define STAGES 3
#define NITER (K_TOT / BK)                   /* 264 */

#define STAGE_BYTES (BM * 128 + BN * 128)    /* 32 KB */
#define SMEM_TOTAL  (STAGES * STAGE_BYTES)   /* 96 KB */

// ---------------- device scratch ----------------
__device__ __align__(128) __half g_A[(size_t)B_DIM * K_TOT];   // 138 MB fp16 A
__device__ __align__(128) __half g_Wt[(size_t)N_TOT * K_TOT];  // 17 MB packed W^T [n][k]
__device__ float g_bias[N_TOT];

// ---------------- PTX helpers ----------------
__device__ __forceinline__ uint32_t smem_u32(const void* p) {
    uint32_t a;
    asm("{ .reg .u64 t; cvta.to.shared.u64 t, %1; cvt.u32.u64 %0, t; }" : "=r"(a) : "l"(p));
    return a;
}
__device__ __forceinline__ void cp_async16(uint32_t saddr, const void* gptr) {
    asm volatile("cp.async.cg.shared.global [%0], [%1], 16;\n" :: "r"(saddr), "l"(gptr));
}
#define CP_COMMIT() asm volatile("cp.async.commit_group;\n" ::: "memory")
#define CP_WAIT(N)  asm volatile("cp.async.wait_group %0;\n" :: "n"(N) : "memory")

__device__ __forceinline__ void ldsm_x4(uint32_t* r, uint32_t saddr) {
    asm volatile("ldmatrix.sync.aligned.m8n8.x4.shared.b16 {%0,%1,%2,%3}, [%4];"
                 : "=r"(r[0]), "=r"(r[1]), "=r"(r[2]), "=r"(r[3]) : "r"(saddr));
}
__device__ __forceinline__ void mma16816(float* d, const uint32_t* a, const uint32_t* b) {
    asm volatile(
        "mma.sync.aligned.m16n8k16.row.col.f32.f16.f16.f32 "
        "{%0,%1,%2,%3}, {%4,%5,%6,%7}, {%8,%9}, {%0,%1,%2,%3};\n"
        : "+f"(d[0]), "+f"(d[1]), "+f"(d[2]), "+f"(d[3])
        : "r"(a[0]), "r"(a[1]), "r"(a[2]), "r"(a[3]), "r"(b[0]), "r"(b[1]));
}

// ---------------- kernel 1: bias vector ----------------
__global__ void bias_kernel(const float* __restrict__ br, const float* __restrict__ bi) {
    int n = blockIdx.x * blockDim.x + threadIdx.x;
    if (n >= N_TOT) return;
    const float* src = (n < O_DIM) ? br : bi;
    int o = n & (O_DIM - 1);
    float s = 0.f;
    for (int i = 0; i < I_DIM; ++i) s += src[i * O_DIM + o];
    g_bias[n] = s;
}

// ---------------- kernel 2: pack W^T [n][k] fp16 ----------------
__global__ void pack_kernel(const float* __restrict__ rw, const float* __restrict__ cw,
                            const float* __restrict__ swr, const float* __restrict__ swi) {
    int gid = blockIdx.x * blockDim.x + threadIdx.x;
    int n = gid / K_TOT;
    int k = gid - n * K_TOT;
    int o = n & (O_DIM - 1);
    bool re = (n < O_DIM);
    float val;
    if (k < K_BASIS) {
        int i = k >> 6, uv = k & 63;
        const float* w = re ? rw : cw;
        val = w[((size_t)(i * O_DIM + o)) * 64 + uv];
    } else if (k < K_BASIS + I_DIM) {
        int i = k - K_BASIS;
        val = re ? swr[i * O_DIM + o] : swi[i * O_DIM + o];
    } else {
        int i = k - K_BASIS - I_DIM;
        val = re ? -swi[i * O_DIM + o] : swr[i * O_DIM + o];
    }
    g_Wt[(size_t)n * K_TOT + k] = __float2half(val);
}

// ---------------- kernel 3: materialize A (vectorized stores) ----------------
__global__ void basis_kernel(const float* __restrict__ x_re, const float* __restrict__ x_im) {
    int b = blockIdx.x;
    int i = threadIdx.x;
    float xr = x_re[b * I_DIM + i];
    float xi = x_im[b * I_DIM + i];
    float eu[8], ev[8];
#pragma unroll
    for (int u = 0; u < 8; ++u) {
        float lu = -2.0f + (float)u * (4.0f / 7.0f);
        float dr = xr - lu;  eu[u] = __expf(-dr * dr);
        float di = xi - lu;  ev[u] = __expf(-di * di);
    }
    uint4* dst = (uint4*)(g_A + (size_t)b * K_TOT + (size_t)i * 64);
#pragma unroll
    for (int u = 0; u < 8; ++u) {
        uint4 row;
        __half2* h = (__half2*)&row;
#pragma unroll
        for (int v = 0; v < 8; v += 2)
            h[v >> 1] = __floats2half2_rn(eu[u] * ev[v], eu[u] * ev[v + 1]);
        dst[u] = row;
    }
    float sr = xr / (1.f + __expf(-xr));
    float si = xi / (1.f + __expf(-xi));
    g_A[(size_t)b * K_TOT + K_BASIS + i]         = __float2half(sr);
    g_A[(size_t)b * K_TOT + K_BASIS + I_DIM + i] = __float2half(si);
}

// ---------------- kernel 4: GEMM (ldmatrix + mma.sync, 3-stage cp.async) ----------------
// stage layout: A tile [128 rows][128B], then B tile [128 rows][128B]
// swizzle: 16B chunk c of row r stored at (c ^ (r & 7))
__device__ __forceinline__ void copy_stage(uint32_t sA, uint32_t sB,
                                           const __half* gA, const __half* gB,
                                           int k0, int tid) {
#pragma unroll
    for (int r = 0; r < 4; ++r) {
        int cc  = tid + (r << 8);          // 0..1023 16B-chunk index per operand
        int row = cc >> 3, ch = cc & 7;
        uint32_t d = (uint32_t)(row << 7) + (uint32_t)((ch ^ (row & 7)) << 4);
        cp_async16(sA + d, gA + (size_t)row * K_TOT + k0 + (ch << 3));
        cp_async16(sB + d, gB + (size_t)row * K_TOT + k0 + (ch << 3));
    }
}

__global__ __launch_bounds__(256, 1)
void gemm_kernel(float* __restrict__ out) {
    extern __shared__ __align__(128) char smem[];
    uint32_t sbase = smem_u32(smem);

    int tid  = threadIdx.x;
    int warp = tid >> 5, lane = tid & 31;
    int bm = blockIdx.x * BM, bn = blockIdx.y * BN;
    int wm = (warp >> 2) * 64;   // warp M offset (0,64)
    int wn = (warp & 3) * 32;    // warp N offset (0..96)

    // ldmatrix per-lane addressing constants
    int ra  = wm + (((lane >> 3) & 1) << 3) + (lane & 7);  // A row (without mi*16)
    int ca  = lane >> 4;                                   // A k16-half chunk select
    int swa = ra & 7;
    int nb  = wn + ((lane >> 4) << 3) + (lane & 7);        // B row (without nn*16)
    int cb  = (lane >> 3) & 1;                             // B k16-half chunk select
    int swb = nb & 7;

    const __half* gA = g_A  + (size_t)bm * K_TOT;
    const __half* gB = g_Wt + (size_t)bn * K_TOT;

    float acc[4][4][4];
#pragma unroll
    for (int mi = 0; mi < 4; ++mi)
#pragma unroll
        for (int ni = 0; ni < 4; ++ni)
#pragma unroll
            for (int c = 0; c < 4; ++c) acc[mi][ni][c] = 0.f;

    // prologue
#pragma unroll
    for (int t = 0; t < STAGES - 1; ++t) {
        copy_stage(sbase + t * STAGE_BYTES, sbase + t * STAGE_BYTES + BM * 128,
                   gA, gB, t * BK, tid);
        CP_COMMIT();
    }

    int s = 0;
    for (int kt = 0; kt < NITER; ++kt) {
        CP_WAIT(STAGES - 2);
        __syncthreads();

        {   // issue next-stage copy first so it overlaps the MMA block
            int knext = kt + STAGES - 1;
            if (knext < NITER) {
                int j = (s == 0) ? STAGES - 1 : s - 1;   // knext % STAGES
                copy_stage(sbase + j * STAGE_BYTES, sbase + j * STAGE_BYTES + BM * 128,
                           gA, gB, knext * BK, tid);
            }
            CP_COMMIT();
        }

        uint32_t baseA = sbase + s * STAGE_BYTES + (uint32_t)(ra << 7);
        uint32_t baseB = sbase + s * STAGE_BYTES + BM * 128 + (uint32_t)(nb << 7);

#pragma unroll
        for (int ks = 0; ks < 4; ++ks) {               // four k16 steps per BK=64
            uint32_t af[4][4];
            uint32_t bf[4][2];
            uint32_t offA = (uint32_t)(((2 * ks + ca) ^ swa) << 4);
            uint32_t offB = (uint32_t)(((2 * ks + cb) ^ swb) << 4);
#pragma unroll
            for (int mi = 0; mi < 4; ++mi)
                ldsm_x4(af[mi], baseA + (uint32_t)(mi * 16 * 128) + offA);
#pragma unroll
            for (int nn = 0; nn < 2; ++nn) {
                uint32_t t4[4];
                ldsm_x4(t4, baseB + (uint32_t)(nn * 16 * 128) + offB);
                bf[2 * nn][0]     = t4[0];
                bf[2 * nn][1]     = t4[1];
                bf[2 * nn + 1][0] = t4[2];
                bf[2 * nn + 1][1] = t4[3];
            }
#pragma unroll
            for (int mi = 0; mi < 4; ++mi)
#pragma unroll
                for (int ni = 0; ni < 4; ++ni)
                    mma16816(acc[mi][ni], af[mi], bf[ni]);
        }
        if (++s == STAGES) s = 0;
    }

    // epilogue: out[(b*O + o)*2 + part] = acc + bias[n]
    int g = lane >> 2, t = lane & 3;
#pragma unroll
    for (int mi = 0; mi < 4; ++mi) {
#pragma unroll
        for (int ni = 0; ni < 4; ++ni) {
            int row0 = bm + wm + mi * 16 + g;
            int col0 = bn + wn + ni * 8 + 2 * t;
            float b0 = g_bias[col0];
            float b1 = g_bias[col0 + 1];
            int o0 = col0 & (O_DIM - 1);
            int part = col0 >> 8;          // whole 128-wide tile is same part
            size_t base0 = ((size_t)row0 * O_DIM + o0) * 2 + part;
            size_t base8 = ((size_t)(row0 + 8) * O_DIM + o0) * 2 + part;
            out[base0]     = acc[mi][ni][0] + b0;
            out[base0 + 2] = acc[mi][ni][1] + b1;
            out[base8]     = acc[mi][ni][2] + b0;
            out[base8 + 2] = acc[mi][ni][3] + b1;
        }
    }
}

// ---------------- launch ----------------
extern "C" void kernel_launch(void* const* d_in, const int* in_sizes, int n_in,
                              void* d_out, int out_size) {
    const float* x_re = (const float*)d_in[0];
    const float* x_im = (const float*)d_in[1];
    const float* rw   = (const float*)d_in[2];
    const float* cw   = (const float*)d_in[3];
    const float* swr  = (const float*)d_in[4];
    const float* swi  = (const float*)d_in[5];
    const float* sbr  = (const float*)d_in[6];
    const float* sbi  = (const float*)d_in[7];
    float* out = (float*)d_out;

    cudaFuncSetAttribute(gemm_kernel, cudaFuncAttributeMaxDynamicSharedMemorySize, SMEM_TOTAL);

    bias_kernel<<<2, 256>>>(sbr, sbi);
    pack_kernel<<<(N_TOT * K_TOT) / 256, 256>>>(rw, cw, swr, swi);
    basis_kernel<<<B_DIM, I_DIM>>>(x_re, x_im);

    dim3 grid(B_DIM / BM, N_TOT / BN);   // 32 x 4 = 128 CTAs
    gemm_kernel<<<grid, 256, SMEM_TOTAL>>>(out);
}